// round 16
// baseline (speedup 1.0000x reference)
#include <cuda_runtime.h>
#include <cuda_bf16.h>
#include <cstdint>
#include <math.h>

// ---------------- problem constants ----------------
#define TT 4096
#define DDIM 2048
#define IDIM 1024
#define EE 8
#define RTOT (2*TT)
#define GTOT (RTOT+TT)

// ---------------- int8 gate_up GEMM tiling: 256 thr, 8 warps (2x4), warp 32x32, CTA 64x128 ----
#define ROW_I 48                  // 32B data + 16B pad; stride 12 words -> conflict-free
#define ARRA_I (64 * ROW_I)       // 3072
#define ARRB_I (128 * ROW_I)      // 6144
#define STAGE_I (2*ARRA_I + 2*ARRB_I)  // 18432
#define SMEM_I (2 * STAGE_I)      // 36864

// ---------------- bf16 down GEMM tiling (R13): 128 thr, 4 warps (2x2), warp 64x64, CTA 128x128 ----
#define ROW_B 80
#define ARR_B (128 * ROW_B)
#define STAGE_B (4 * ARR_B)
#define SMEM_B (2 * STAGE_B)      // 81920
#define NCHUNK 16

// ---------------- scratch ----------------
__device__ signed char g_qxh[(size_t)TT * DDIM];
__device__ signed char g_qxl[(size_t)TT * DDIM];
__device__ float g_sx[TT];                                  // x row scale (max/127)
__device__ signed char g_qguh[(size_t)9 * 2048 * 2048];     // gate_up^T int8 hi
__device__ signed char g_qgul[(size_t)9 * 2048 * 2048];
__device__ int g_sbmax[9 * 2048];                           // per-n-row |w| max (float bits)
__device__ unsigned short g_bdnh[(size_t)9 * 2048 * 1024];  // down^T bf16 hi
__device__ unsigned short g_bdnl[(size_t)9 * 2048 * 1024];
__device__ unsigned short g_rhh[(size_t)GTOT * 1024];
__device__ unsigned short g_rhl[(size_t)GTOT * 1024];
__device__ float g_do[(size_t)GTOT * 2048];
__device__ int   g_e0[TT], g_e1[TT];
__device__ float g_p0[TT], g_p1[TT];
__device__ int   g_cnt[EE];
__device__ int   g_ltok[EE * TT];
__device__ float g_lp[EE * TT];
__device__ int   g_sl0[TT], g_sl1[TT];

__device__ __forceinline__ float siluf(float v) { return v / (1.0f + __expf(-v)); }

__device__ __forceinline__ void splitbf(float v, unsigned short& h, unsigned short& l) {
    __nv_bfloat16 bh = __float2bfloat16(v);
    float rem = v - __bfloat162float(bh);
    __nv_bfloat16 bl = __float2bfloat16(rem);
    h = __bfloat16_as_ushort(bh);
    l = __bfloat16_as_ushort(bl);
}

__device__ __forceinline__ void quant2(float v, float inv_s, signed char& qh, signed char& ql) {
    float q = v * inv_s;                   // in [-127, 127]
    int ih = __float2int_rn(q);
    int il = __float2int_rn((q - (float)ih) * 127.0f);
    qh = (signed char)ih; ql = (signed char)il;
}

__device__ __forceinline__ uint32_t smem_u32(const void* p) {
    uint32_t a;
    asm("{ .reg .u64 t; cvta.to.shared.u64 t, %1; cvt.u32.u64 %0, t; }" : "=r"(a) : "l"(p));
    return a;
}

#define CP16(dst, src) \
    asm volatile("cp.async.cg.shared.global [%0], [%1], 16;" :: "r"(dst), "l"(src) : "memory")
#define CP_COMMIT() asm volatile("cp.async.commit_group;" ::: "memory")
#define CP_WAIT(n)  asm volatile("cp.async.wait_group %0;" :: "n"(n) : "memory")

__device__ __forceinline__ void mma16(float* c, const uint32_t* a, const uint32_t* b) {
    asm volatile(
        "mma.sync.aligned.m16n8k16.row.col.f32.bf16.bf16.f32 "
        "{%0,%1,%2,%3}, {%4,%5,%6,%7}, {%8,%9}, {%0,%1,%2,%3};"
        : "+f"(c[0]), "+f"(c[1]), "+f"(c[2]), "+f"(c[3])
        : "r"(a[0]), "r"(a[1]), "r"(a[2]), "r"(a[3]), "r"(b[0]), "r"(b[1]));
}

__device__ __forceinline__ void mma_s8(int* c, const uint32_t* a, const uint32_t* b) {
    asm volatile(
        "mma.sync.aligned.m16n8k32.row.col.s32.s8.s8.s32 "
        "{%0,%1,%2,%3}, {%4,%5,%6,%7}, {%8,%9}, {%0,%1,%2,%3};"
        : "+r"(c[0]), "+r"(c[1]), "+r"(c[2]), "+r"(c[3])
        : "r"(a[0]), "r"(a[1]), "r"(a[2]), "r"(a[3]), "r"(b[0]), "r"(b[1]));
}

__device__ __forceinline__ void ldsm4(uint32_t* r, uint32_t addr) {
    asm volatile("ldmatrix.sync.aligned.m8n8.x4.shared.b16 {%0,%1,%2,%3}, [%4];"
        : "=r"(r[0]), "=r"(r[1]), "=r"(r[2]), "=r"(r[3]) : "r"(addr));
}
__device__ __forceinline__ void ldsm2(uint32_t* r, uint32_t addr) {
    asm volatile("ldmatrix.sync.aligned.m8n8.x2.shared.b16 {%0,%1}, [%2];"
        : "=r"(r[0]), "=r"(r[1]) : "r"(addr));
}

// ---------------- launch 0: router + zero weight-scale maxes ----------------
#define NB_RT 512
#define NB_Z  72          // 18432 / 256
__global__ void router_zero_kernel(const float* __restrict__ x, const float* __restrict__ rw) {
    int b = blockIdx.x;
    if (b >= NB_RT) {     // zero g_sbmax
        int i = (b - NB_RT) * 256 + threadIdx.x;
        if (i < 9 * 2048) g_sbmax[i] = 0;
        return;
    }
    int gwarp = b * 8 + (threadIdx.x >> 5);
    int lane = threadIdx.x & 31;
    const float* xr = x + (size_t)gwarp * DDIM;
    float acc[8] = {0.f,0.f,0.f,0.f,0.f,0.f,0.f,0.f};
    for (int d = lane; d < DDIM; d += 32) {
        float xv = xr[d];
        const float4* r4 = (const float4*)(rw + (size_t)d * EE);
        float4 a = r4[0], bb = r4[1];
        acc[0] += xv * a.x;  acc[1] += xv * a.y;  acc[2] += xv * a.z;  acc[3] += xv * a.w;
        acc[4] += xv * bb.x; acc[5] += xv * bb.y; acc[6] += xv * bb.z; acc[7] += xv * bb.w;
    }
    #pragma unroll
    for (int e = 0; e < 8; e++)
        #pragma unroll
        for (int s = 16; s > 0; s >>= 1)
            acc[e] += __shfl_xor_sync(0xffffffffu, acc[e], s);
    if (lane == 0) {
        int i0 = 0; float v0 = acc[0];
        #pragma unroll
        for (int e = 1; e < 8; e++) if (acc[e] > v0) { v0 = acc[e]; i0 = e; }
        int i1 = -1; float v1 = -3.4e38f;
        #pragma unroll
        for (int e = 0; e < 8; e++) if (e != i0 && acc[e] > v1) { v1 = acc[e]; i1 = e; }
        g_e0[gwarp] = i0; g_e1[gwarp] = i1;
        g_p0[gwarp] = 1.0f / (1.0f + __expf(-v0));
        g_p1[gwarp] = 1.0f / (1.0f + __expf(-v1));
    }
}

// ---------------- launch 1: x int8 quant + gu weight maxes + dn bf16 split ----------------
#define NB_XQ 4096
#define NB_GU 36864
#define NB_DN 18432
__global__ void pass1_kernel(const float* __restrict__ x,
                             const float* __restrict__ guw,
                             const float* __restrict__ dw,
                             const float* __restrict__ sgw,
                             const float* __restrict__ suw,
                             const float* __restrict__ sdw) {
    __shared__ float tile[32][33];
    __shared__ float red[8];
    const int b = blockIdx.x;
    const int tid = threadIdx.x;

    if (b < NB_XQ) {      // per-token int8 quantization
        int tok = b;
        const float* xr = x + (size_t)tok * DDIM;
        float4 v0 = *(const float4*)(xr + tid * 8);
        float4 v1 = *(const float4*)(xr + tid * 8 + 4);
        float mx = fmaxf(fmaxf(fabsf(v0.x), fabsf(v0.y)), fmaxf(fabsf(v0.z), fabsf(v0.w)));
        mx = fmaxf(mx, fmaxf(fmaxf(fabsf(v1.x), fabsf(v1.y)), fmaxf(fabsf(v1.z), fabsf(v1.w))));
        #pragma unroll
        for (int s = 16; s > 0; s >>= 1) mx = fmaxf(mx, __shfl_xor_sync(0xffffffffu, mx, s));
        if ((tid & 31) == 0) red[tid >> 5] = mx;
        __syncthreads();
        if (tid == 0) {
            float m = red[0];
            #pragma unroll
            for (int w = 1; w < 8; w++) m = fmaxf(m, red[w]);
            m = fmaxf(m, 1e-30f);
            red[0] = m;
            g_sx[tok] = m * (1.0f / 127.0f);
        }
        __syncthreads();
        float inv_s = 127.0f / red[0];
        signed char h[8], l[8];
        quant2(v0.x, inv_s, h[0], l[0]); quant2(v0.y, inv_s, h[1], l[1]);
        quant2(v0.z, inv_s, h[2], l[2]); quant2(v0.w, inv_s, h[3], l[3]);
        quant2(v1.x, inv_s, h[4], l[4]); quant2(v1.y, inv_s, h[5], l[5]);
        quant2(v1.z, inv_s, h[6], l[6]); quant2(v1.w, inv_s, h[7], l[7]);
        size_t o = (size_t)tok * DDIM + tid * 8;
        *(char4*)(g_qxh + o)     = make_char4(h[0], h[1], h[2], h[3]);
        *(char4*)(g_qxh + o + 4) = make_char4(h[4], h[5], h[6], h[7]);
        *(char4*)(g_qxl + o)     = make_char4(l[0], l[1], l[2], l[3]);
        *(char4*)(g_qxl + o + 4) = make_char4(l[4], l[5], l[6], l[7]);
        return;
    }
    const int tx = tid & 31, ty = tid >> 5;
    if (b < NB_XQ + NB_GU) {   // gu weight per-n-row max (atomicMax)
        int bb = b - NB_XQ;
        int bx = bb & 63, by = (bb >> 6) & 63, e = bb >> 12;
        int n0 = bx * 32, k0 = by * 32;
        const float* src; int ld, nsrc0;
        if (e < 8)          { src = guw + (size_t)e * 2048 * 2048; ld = 2048; nsrc0 = n0; }
        else if (n0 < 1024) { src = sgw; ld = 1024; nsrc0 = n0; }
        else                { src = suw; ld = 1024; nsrc0 = n0 - 1024; }
        #pragma unroll
        for (int j = 0; j < 4; j++) {
            int k = k0 + ty + j * 8;
            tile[ty + j * 8][tx] = src[(size_t)k * ld + nsrc0 + tx];
        }
        __syncthreads();
        #pragma unroll
        for (int j = 0; j < 4; j++) {
            int n = n0 + ty + j * 8;
            float v = fabsf(tile[tx][ty + j * 8]);
            #pragma unroll
            for (int s = 16; s > 0; s >>= 1) v = fmaxf(v, __shfl_xor_sync(0xffffffffu, v, s));
            if (tx == 0) atomicMax(&g_sbmax[e * 2048 + n], __float_as_int(v));
        }
        return;
    }
    {   // dn bf16 split (unchanged)
        int bb = b - NB_XQ - NB_GU;
        int bx = bb & 63, by = (bb >> 6) & 31, e = bb >> 11;
        int n0 = bx * 32, k0 = by * 32;
        const float* src = (e < 8) ? (dw + (size_t)e * 1024 * 2048) : sdw;
        #pragma unroll
        for (int j = 0; j < 4; j++) {
            int k = k0 + ty + j * 8;
            tile[ty + j * 8][tx] = src[(size_t)k * 2048 + n0 + tx];
        }
        __syncthreads();
        #pragma unroll
        for (int j = 0; j < 4; j++) {
            int n = n0 + ty + j * 8;
            float v = tile[tx][ty + j * 8];
            unsigned short h, l;
            splitbf(v, h, l);
            size_t di = ((size_t)e * 2048 + n) * 1024 + k0 + tx;
            g_bdnh[di] = h; g_bdnl[di] = l;
        }
    }
}

// ---------------- launch 2: gu weight int8 quantize + build lists ----------------
__global__ void pass2_kernel(const float* __restrict__ guw,
                             const float* __restrict__ sgw,
                             const float* __restrict__ suw) {
    __shared__ float tile[32][33];
    const int b = blockIdx.x;
    const int tid = threadIdx.x;

    if (b < NB_GU) {
        int bx = b & 63, by = (b >> 6) & 63, e = b >> 12;
        int n0 = bx * 32, k0 = by * 32;
        const float* src; int ld, nsrc0;
        if (e < 8)          { src = guw + (size_t)e * 2048 * 2048; ld = 2048; nsrc0 = n0; }
        else if (n0 < 1024) { src = sgw; ld = 1024; nsrc0 = n0; }
        else                { src = suw; ld = 1024; nsrc0 = n0 - 1024; }
        const int tx = tid & 31, ty = tid >> 5;
        #pragma unroll
        for (int j = 0; j < 4; j++) {
            int k = k0 + ty + j * 8;
            tile[ty + j * 8][tx] = src[(size_t)k * ld + nsrc0 + tx];
        }
        __syncthreads();
        #pragma unroll
        for (int j = 0; j < 4; j++) {
            int n = n0 + ty + j * 8;
            float mx = fmaxf(__int_as_float(g_sbmax[e * 2048 + n]), 1e-30f);
            float inv_s = 127.0f / mx;
            float v = tile[tx][ty + j * 8];
            signed char qh, ql;
            quant2(v, inv_s, qh, ql);
            size_t di = ((size_t)e * 2048 + n) * 2048 + k0 + tx;
            g_qguh[di] = qh; g_qgul[di] = ql;
        }
        return;
    }
    // build_lists blocks (8)
    int e = b - NB_GU;
    int lane = tid & 31, wid = tid >> 5;
    __shared__ int wsum[8];
    __shared__ int base_s;
    if (tid == 0) base_s = 0;
    __syncthreads();
    for (int t0 = 0; t0 < TT; t0 += 256) {
        int t = t0 + tid;
        bool sel = false; float p = 0.f; bool first = false;
        if (g_e0[t] == e)      { sel = true; p = g_p0[t]; first = true; }
        else if (g_e1[t] == e) { sel = true; p = g_p1[t]; }
        unsigned m = __ballot_sync(0xffffffffu, sel);
        int rank = __popc(m & ((1u << lane) - 1));
        if (lane == 0) wsum[wid] = __popc(m);
        __syncthreads();
        int woff = 0;
        #pragma unroll
        for (int w = 0; w < 8; w++) if (w < wid) woff += wsum[w];
        if (sel) {
            int idx = base_s + woff + rank;
            g_ltok[e * TT + idx] = t;
            g_lp[e * TT + idx]   = p;
            if (first) g_sl0[t] = idx; else g_sl1[t] = idx;
        }
        __syncthreads();
        if (tid == 0) {
            int tot = 0;
            #pragma unroll
            for (int w = 0; w < 8; w++) tot += wsum[w];
            base_s += tot;
        }
        __syncthreads();
    }
    if (tid == 0) g_cnt[e] = base_s;
}

__device__ __forceinline__ int expert_off(int e) {
    int o = 0;
    #pragma unroll
    for (int i = 0; i < EE; i++) if (i < e) o += g_cnt[i];
    return o;
}

// ---------------- launch 3: int8 gate_up GEMM + scales + SiLU + bf16-split h ----------------
// grid (16, 64, 9): x = 64-gate-col tile, y = 64-row tile, z = expert
__global__ void __launch_bounds__(256, 2)
gemm_gu_i8()
{
    extern __shared__ char smem[];
    const uint32_t sb = smem_u32(smem);
    const int tid = threadIdx.x;
    const int e = blockIdx.z;
    const int row0 = blockIdx.y * 64;
    const int col0g = blockIdx.x * 64;

    int M, soff;
    const float* lpp = nullptr;
    const int* ltok = nullptr;
    if (e < 8) { M = g_cnt[e]; soff = expert_off(e); ltok = g_ltok + e * TT; lpp = g_lp + e * TT; }
    else       { M = TT; soff = RTOT; }
    if (row0 >= M) return;

    // cp.async plan: 3 chunks/thread (A: 256 chunks, B: 512 chunks)
    const char* src[3]; uint32_t dst[3];
    #pragma unroll
    for (int i = 0; i < 3; i++) {
        int idx = tid + i * 256;
        if (idx < 256) {          // A: 64 rows x (2 arr x 2 ch)
            int r = idx >> 2, sub = idx & 3;
            int arr = sub >> 1, ch = sub & 1;
            int gr = row0 + r;
            size_t tok = (e < 8) ? (size_t)((gr < M) ? ltok[gr] : 0) : (size_t)gr;
            const signed char* rowp = ((arr == 0) ? g_qxh : g_qxl) + tok * DDIM;
            src[i] = (const char*)rowp + ch * 16;
            dst[i] = sb + (uint32_t)(arr * ARRA_I + r * ROW_I + ch * 16);
        } else {                  // B: 128 rows x (2 arr x 2 ch)
            int bi = idx - 256;
            int r = bi >> 2, sub = bi & 3;
            int arr = sub >> 1, ch = sub & 1;
            int grp = r >> 5, w = r & 31;
            int ncol = (w < 16) ? (col0g + grp * 16 + w)
                                : (1024 + col0g + grp * 16 + (w - 16));
            const signed char* rowp = ((arr == 0) ? g_qguh : g_qgul) + ((size_t)e * 2048 + ncol) * 2048;
            src[i] = (const char*)rowp + ch * 16;
            dst[i] = sb + (uint32_t)(2 * ARRA_I + arr * ARRB_I + r * ROW_I + ch * 16);
        }
    }

    const int lane = tid & 31;
    const int g = lane >> 2, t = lane & 3;
    const int wm = (tid >> 5) & 1, wn = (tid >> 5) >> 1;   // 2 x 4 warps

    const uint32_t aoff = (uint32_t)((wm * 32 + (lane & 7) + ((lane >> 3) & 1) * 8) * ROW_I
                                     + (lane >> 4) * 16);
    const uint32_t boff = (uint32_t)((wn * 32 + (lane & 7)) * ROW_I + ((lane >> 3) & 1) * 16);

    int acc_hh[2][4][4], acc_cr[2][4][4];
    #pragma unroll
    for (int mi = 0; mi < 2; mi++)
        #pragma unroll
        for (int ni = 0; ni < 4; ni++)
            #pragma unroll
            for (int r = 0; r < 4; r++) { acc_hh[mi][ni][r] = 0; acc_cr[mi][ni][r] = 0; }

    #pragma unroll
    for (int i = 0; i < 3; i++) { CP16(dst[i], src[i]); src[i] += 32; }
    CP_COMMIT();

    const int NK = DDIM / 32;   // 64
    for (int it = 0; it < NK; it++) {
        CP_WAIT(0);
        __syncthreads();
        if (it + 1 < NK) {
            uint32_t so = (uint32_t)(((it + 1) & 1) * STAGE_I);
            #pragma unroll
            for (int i = 0; i < 3; i++) { CP16(dst[i] + so, src[i]); src[i] += 32; }
            CP_COMMIT();
        }
        const uint32_t base = sb + (uint32_t)((it & 1) * STAGE_I);
        const uint32_t Ah = base + aoff;
        const uint32_t Al = Ah + ARRA_I;
        const uint32_t Bh = base + 2 * ARRA_I + boff;
        const uint32_t Bl = Bh + ARRB_I;

        uint32_t bhf[4][2], blf[4][2];
        #pragma unroll
        for (int ni = 0; ni < 4; ni++) {
            ldsm2(bhf[ni], Bh + ni * (8 * ROW_I));
            ldsm2(blf[ni], Bl + ni * (8 * ROW_I));
        }
        #pragma unroll
        for (int mi = 0; mi < 2; mi++) {
            uint32_t ah[4], al[4];
            ldsm4(ah, Ah + mi * (16 * ROW_I));
            ldsm4(al, Al + mi * (16 * ROW_I));
            #pragma unroll
            for (int ni = 0; ni < 4; ni++) {
                mma_s8(acc_hh[mi][ni], ah, bhf[ni]);
                mma_s8(acc_cr[mi][ni], ah, blf[ni]);
                mma_s8(acc_cr[mi][ni], al, bhf[ni]);
            }
        }
    }

    // epilogue: reconstruct fp32, apply p, SiLU, split bf16, store h
    // gate acc at ni {0,1}; up at ni {2,3} (same col offset - 16 rows)
    const float inv127 = 1.0f / 127.0f;
    #pragma unroll
    for (int mi = 0; mi < 2; mi++) {
        int grb = row0 + wm * 32 + mi * 16 + g;
        #pragma unroll
        for (int pass = 0; pass < 2; pass++) {
            int gr = grb + pass * 8;
            if (gr < M) {
                float p; size_t tok;
                if (e < 8) { p = lpp[gr]; tok = (size_t)ltok[gr]; }
                else       { p = 1.f;     tok = (size_t)gr; }
                float sxa = g_sx[tok];
                size_t slot = (size_t)(soff + gr);
                #pragma unroll
                for (int ni = 0; ni < 2; ni++) {
                    int colb = col0g + wn * 16 + ni * 8 + 2 * t;
                    float sg0 = __int_as_float(g_sbmax[e * 2048 + colb])        * inv127;
                    float sg1 = __int_as_float(g_sbmax[e * 2048 + colb + 1])    * inv127;
                    float su0 = __int_as_float(g_sbmax[e * 2048 + 1024 + colb])     * inv127;
                    float su1 = __int_as_float(g_sbmax[e * 2048 + 1024 + colb + 1]) * inv127;
                    float gv0 = p * sxa * sg0 * ((float)acc_hh[mi][ni][pass*2+0] + (float)acc_cr[mi][ni][pass*2+0] * inv127);
                    float gv1 = p * sxa * sg1 * ((float)acc_hh[mi][ni][pass*2+1] + (float)acc_cr[mi][ni][pass*2+1] * inv127);
                    float uv0 = p * sxa * su0 * ((float)acc_hh[mi][ni+2][pass*2+0] + (float)acc_cr[mi][ni+2][pass*2+0] * inv127);
                    float uv1 = p * sxa * su1 * ((float)acc_hh[mi][ni+2][pass*2+1] + (float)acc_cr[mi][ni+2][pass*2+1] * inv127);
                    float h0 = siluf(gv0) * uv0;
                    float h1 = siluf(gv1) * uv1;
                    unsigned short h0h, h0l, h1h, h1l;
                    splitbf(h0, h0h, h0l);
                    splitbf(h1, h1h, h1l);
                    ushort2 hh; hh.x = h0h; hh.y = h1h;
                    ushort2 hl; hl.x = h0l; hl.y = h1l;
                    *(ushort2*)(g_rhh + slot * 1024 + colb) = hh;
                    *(ushort2*)(g_rhl + slot * 1024 + colb) = hl;
                }
            }
        }
    }
}

// ---------------- launch 4: bf16x2 down GEMM (R13 config). grid (16, 32, 9) ----------------
__global__ void __launch_bounds__(128, 2)
gemm_down()
{
    const int KD = 1024;
    extern __shared__ char smem[];
    const uint32_t sb = smem_u32(smem);
    const int tid = threadIdx.x;
    const int e = blockIdx.z;
    const int row0 = blockIdx.y * 128;
    const int col0 = blockIdx.x * 128;

    int M, soff;
    if (e < 8) { M = g_cnt[e]; soff = expert_off(e); } else { M = TT; soff = RTOT; }
    if (row0 >= M) return;

    const char* src[NCHUNK]; uint32_t dst[NCHUNK];
    #pragma unroll
    for (int i = 0; i < NCHUNK; i++) {
        int idx = tid + i * 128;
        const unsigned short* rowp;
        if (idx < 1024) {
            int arr = idx >> 9, ci = idx & 511;
            int r = ci >> 2, ch = ci & 3;
            int gr = row0 + r;
            size_t slot = (size_t)(soff + ((gr < M) ? gr : 0));
            rowp = ((arr == 0) ? g_rhh : g_rhl) + slot * 1024;
            src[i] = (const char*)rowp + ch * 16;
            dst[i] = sb + (uint32_t)(arr * ARR_B + r * ROW_B + ch * 16);
        } else {
            int bi = idx - 1024;
            int arr = bi >> 9, ci = bi & 511;
            int r = ci >> 2, ch = ci & 3;
            rowp = ((arr == 0) ? g_bdnh : g_bdnl) + ((size_t)e * 2048 + col0 + r) * (size_t)KD;
            src[i] = (const char*)rowp + ch * 16;
            dst[i] = sb + (uint32_t)(2 * ARR_B + arr * ARR_B + r * ROW_B + ch * 16);
        }
    }

    const int lane = tid & 31;
    const int g = lane >> 2, t = lane & 3;
    const int wm = (tid >> 5) & 1, wn = (tid >> 5) >> 1;

    const uint32_t aoff = (uint32_t)((wm * 64 + (lane & 7) + ((lane >> 3) & 1) * 8) * ROW_B
                                     + (lane >> 4) * 16);
    const uint32_t boff = (uint32_t)((wn * 64 + (lane & 7)) * ROW_B + ((lane >> 3) & 1) * 16);

    float acc[4][8][4];
    #pragma unroll
    for (int mi = 0; mi < 4; mi++)
        #pragma unroll
        for (int ni = 0; ni < 8; ni++)
            #pragma unroll
            for (int r = 0; r < 4; r++) acc[mi][ni][r] = 0.f;

    #pragma unroll
    for (int i = 0; i < NCHUNK; i++) { CP16(dst[i], src[i]); src[i] += 64; }
    CP_COMMIT();

    const int NK = KD / 32;
    for (int it = 0; it < NK; it++) {
        CP_WAIT(0);
        __syncthreads();
        if (it + 1 < NK) {
            uint32_t so = (uint32_t)(((it + 1) & 1) * STAGE_B);
            #pragma unroll
            for (int i = 0; i < NCHUNK; i++) { CP16(dst[i] + so, src[i]); src[i] += 64; }
            CP_COMMIT();
        }
        const uint32_t base = sb + (uint32_t)((it & 1) * STAGE_B);
        const uint32_t Ah = base + aoff;
        const uint32_t Al = Ah + ARR_B;
        const uint32_t Bh = base + 2 * ARR_B + boff;
        const uint32_t Bl = Bh + ARR_B;
        #pragma unroll
        for (int s = 0; s < 2; s++) {
            uint32_t bhf[8][2], blf[8][2];
            #pragma unroll
            for (int ni = 0; ni < 8; ni++) {
                ldsm2(bhf[ni], Bh + ni * (8 * ROW_B) + s * 32);
                ldsm2(blf[ni], Bl + ni * (8 * ROW_B) + s * 32);
            }
            #pragma unroll
            for (int mi = 0; mi < 4; mi++) {
                uint32_t ah[4], al[4];
                ldsm4(ah, Ah + mi * (16 * ROW_B) + s * 32);
                ldsm4(al, Al + mi * (16 * ROW_B) + s * 32);
                #pragma unroll
                for (int ni = 0; ni < 8; ni++) {
                    mma16(acc[mi][ni], ah, bhf[ni]);
                    mma16(acc[mi][ni], ah, blf[ni]);
                    mma16(acc[mi][ni], al, bhf[ni]);
                }
            }
        }
    }

    #pragma unroll
    for (int mi = 0; mi < 4; mi++) {
        int gr0 = row0 + wm * 64 + mi * 16 + g;
        int gr1 = gr0 + 8;
        bool v0 = gr0 < M, v1 = gr1 < M;
        float* d0 = g_do + (size_t)(soff + gr0) * 2048 + col0 + wn * 64;
        float* d1 = g_do + (size_t)(soff + gr1) * 2048 + col0 + wn * 64;
        #pragma unroll
        for (int ni = 0; ni < 8; ni++) {
            int cc = ni * 8 + 2 * t;
            if (v0) { float2 v; v.x = acc[mi][ni][0]; v.y = acc[mi][ni][1]; *(float2*)(d0 + cc) = v; }
            if (v1) { float2 v; v.x = acc[mi][ni][2]; v.y = acc[mi][ni][3]; *(float2*)(d1 + cc) = v; }
        }
    }
}

// ---------------- launch 5: combine ----------------
__global__ void combine_kernel(float* __restrict__ out) {
    int t = blockIdx.x;
    int c = threadIdx.x * 8;
    int s0 = expert_off(g_e0[t]) + g_sl0[t];
    int s1 = expert_off(g_e1[t]) + g_sl1[t];
    const float* pa = g_do + (size_t)(RTOT + t) * 2048 + c;
    const float* pb = g_do + (size_t)s0 * 2048 + c;
    const float* pc = g_do + (size_t)s1 * 2048 + c;
    float* po = out + (size_t)t * 2048 + c;
    #pragma unroll
    for (int j = 0; j < 2; j++) {
        float4 a = *(const float4*)(pa + j * 4);
        float4 b = *(const float4*)(pb + j * 4);
        float4 d = *(const float4*)(pc + j * 4);
        float4 o;
        o.x = a.x + b.x + d.x; o.y = a.y + b.y + d.y;
        o.z = a.z + b.z + d.z; o.w = a.w + b.w + d.w;
        *(float4*)(po + j * 4) = o;
    }
}

// ---------------- launch ----------------
extern "C" void kernel_launch(void* const* d_in, const int* in_sizes, int n_in,
                              void* d_out, int out_size) {
    const float* x   = (const float*)d_in[0];
    const float* rw  = (const float*)d_in[1];
    const float* guw = (const float*)d_in[2];
    const float* dw  = (const float*)d_in[3];
    const float* sgw = (const float*)d_in[4];
    const float* suw = (const float*)d_in[5];
    const float* sdw = (const float*)d_in[6];
    float* out = (float*)d_out;

    cudaFuncSetAttribute(gemm_gu_i8, cudaFuncAttributeMaxDynamicSharedMemorySize, SMEM_I);
    cudaFuncSetAttribute(gemm_down,  cudaFuncAttributeMaxDynamicSharedMemorySize, SMEM_B);

    router_zero_kernel<<<NB_RT + NB_Z, 256>>>(x, rw);                          // #0
    pass1_kernel<<<NB_XQ + NB_GU + NB_DN, 256>>>(x, guw, dw, sgw, suw, sdw);   // #1
    pass2_kernel<<<NB_GU + EE, 256>>>(guw, sgw, suw);                          // #2
    gemm_gu_i8<<<dim3(16, 64, 9), 256, SMEM_I>>>();                            // #3 (profiled)
    gemm_down<<<dim3(16, 32, 9), 128, SMEM_B>>>();                             // #4
    combine_kernel<<<TT, 256>>>(out);                                          // #5
}

// round 17
// speedup vs baseline: 1.9731x; 1.9731x over previous
#include <cuda_runtime.h>
#include <cuda_bf16.h>
#include <cstdint>
#include <math.h>

// ---------------- problem constants ----------------
#define TT 4096
#define DDIM 2048
#define IDIM 1024
#define EE 8
#define RTOT (2*TT)
#define GTOT (RTOT+TT)

// ---------------- GEMM tiling: CTA 128 thr = 4 warps (2x2), warp 64x64, CTA tile 128x128 ----------------
#define KT 32
#define ROW_B 80                 // 64B data + 16B pad; stride 20 words -> conflict-free
#define ARR_B (128 * ROW_B)      // 10240 per operand array
#define STAGE_B (4 * ARR_B)      // Ahi|Alo|Bhi|Blo = 40960
#define SMEM_BYTES (2 * STAGE_B) // 81920 (x2 CTAs = 163840 <= 228K)
#define NCHUNK 16

// ---------------- scratch ----------------
__device__ unsigned short g_xhi[(size_t)TT * DDIM];
__device__ unsigned short g_xlo[(size_t)TT * DDIM];
__device__ unsigned short g_bguh[(size_t)9 * 2048 * 2048];  // gate_up^T [e][n][k] hi
__device__ unsigned short g_bgul[(size_t)9 * 2048 * 2048];
__device__ unsigned short g_bdnh[(size_t)9 * 2048 * 1024];  // down^T [e][n][k] hi
__device__ unsigned short g_bdnl[(size_t)9 * 2048 * 1024];
__device__ unsigned short g_rhh[(size_t)GTOT * 1024];       // h split hi
__device__ unsigned short g_rhl[(size_t)GTOT * 1024];
__device__ int   g_e0[TT], g_e1[TT];
__device__ float g_p0[TT], g_p1[TT];
__device__ int   g_cnt[EE];
__device__ int   g_off[EE];
__device__ int   g_ltok[EE * TT];
__device__ float g_lp[EE * TT];
__device__ int   g_sl0[TT], g_sl1[TT];

__device__ __forceinline__ float siluf(float v) { return v / (1.0f + __expf(-v)); }

__device__ __forceinline__ void splitbf(float v, unsigned short& h, unsigned short& l) {
    __nv_bfloat16 bh = __float2bfloat16(v);
    float rem = v - __bfloat162float(bh);
    __nv_bfloat16 bl = __float2bfloat16(rem);
    h = __bfloat16_as_ushort(bh);
    l = __bfloat16_as_ushort(bl);
}

__device__ __forceinline__ uint32_t smem_u32(const void* p) {
    uint32_t a;
    asm("{ .reg .u64 t; cvta.to.shared.u64 t, %1; cvt.u32.u64 %0, t; }" : "=r"(a) : "l"(p));
    return a;
}

#define CP16(dst, src) \
    asm volatile("cp.async.cg.shared.global [%0], [%1], 16;" :: "r"(dst), "l"(src) : "memory")
#define CP_COMMIT() asm volatile("cp.async.commit_group;" ::: "memory")
#define CP_WAIT(n)  asm volatile("cp.async.wait_group %0;" :: "n"(n) : "memory")

__device__ __forceinline__ void mma16(float* c, const uint32_t* a, const uint32_t* b) {
    asm volatile(
        "mma.sync.aligned.m16n8k16.row.col.f32.bf16.bf16.f32 "
        "{%0,%1,%2,%3}, {%4,%5,%6,%7}, {%8,%9}, {%0,%1,%2,%3};"
        : "+f"(c[0]), "+f"(c[1]), "+f"(c[2]), "+f"(c[3])
        : "r"(a[0]), "r"(a[1]), "r"(a[2]), "r"(a[3]), "r"(b[0]), "r"(b[1]));
}

__device__ __forceinline__ void ldsm4(uint32_t* r, uint32_t addr) {
    asm volatile("ldmatrix.sync.aligned.m8n8.x4.shared.b16 {%0,%1,%2,%3}, [%4];"
        : "=r"(r[0]), "=r"(r[1]), "=r"(r[2]), "=r"(r[3]) : "r"(addr));
}
__device__ __forceinline__ void ldsm2(uint32_t* r, uint32_t addr) {
    asm volatile("ldmatrix.sync.aligned.m8n8.x2.shared.b16 {%0,%1}, [%2];"
        : "=r"(r[0]), "=r"(r[1]) : "r"(addr));
}

// ---------------- launch 0: router ----------------
__global__ void router_kernel(const float* __restrict__ x, const float* __restrict__ rw) {
    int gwarp = (blockIdx.x * blockDim.x + threadIdx.x) >> 5;
    int lane = threadIdx.x & 31;
    if (gwarp >= TT) return;
    const float* xr = x + (size_t)gwarp * DDIM;
    float acc[8] = {0.f,0.f,0.f,0.f,0.f,0.f,0.f,0.f};
    for (int d = lane; d < DDIM; d += 32) {
        float xv = xr[d];
        const float4* r4 = (const float4*)(rw + (size_t)d * EE);
        float4 a = r4[0], b = r4[1];
        acc[0] += xv * a.x; acc[1] += xv * a.y; acc[2] += xv * a.z; acc[3] += xv * a.w;
        acc[4] += xv * b.x; acc[5] += xv * b.y; acc[6] += xv * b.z; acc[7] += xv * b.w;
    }
    #pragma unroll
    for (int e = 0; e < 8; e++)
        #pragma unroll
        for (int s = 16; s > 0; s >>= 1)
            acc[e] += __shfl_xor_sync(0xffffffffu, acc[e], s);
    if (lane == 0) {
        int i0 = 0; float v0 = acc[0];
        #pragma unroll
        for (int e = 1; e < 8; e++) if (acc[e] > v0) { v0 = acc[e]; i0 = e; }
        int i1 = -1; float v1 = -3.4e38f;
        #pragma unroll
        for (int e = 0; e < 8; e++) if (e != i0 && acc[e] > v1) { v1 = acc[e]; i1 = e; }
        g_e0[gwarp] = i0; g_e1[gwarp] = i1;
        g_p0[gwarp] = 1.0f / (1.0f + __expf(-v0));
        g_p1[gwarp] = 1.0f / (1.0f + __expf(-v1));
    }
}

// ---------------- launch 1: deterministic compaction ----------------
__global__ void build_lists_kernel() {
    int e = blockIdx.x;
    int tid = threadIdx.x;
    int lane = tid & 31, wid = tid >> 5;
    __shared__ int wsum[8];
    __shared__ int base_s;
    if (tid == 0) base_s = 0;
    __syncthreads();
    for (int t0 = 0; t0 < TT; t0 += 256) {
        int t = t0 + tid;
        bool sel = false; float p = 0.f; bool first = false;
        if (g_e0[t] == e)      { sel = true; p = g_p0[t]; first = true; }
        else if (g_e1[t] == e) { sel = true; p = g_p1[t]; }
        unsigned m = __ballot_sync(0xffffffffu, sel);
        int rank = __popc(m & ((1u << lane) - 1));
        if (lane == 0) wsum[wid] = __popc(m);
        __syncthreads();
        int woff = 0;
        #pragma unroll
        for (int w = 0; w < 8; w++) if (w < wid) woff += wsum[w];
        if (sel) {
            int idx = base_s + woff + rank;
            g_ltok[e * TT + idx] = t;
            g_lp[e * TT + idx]   = p;
            if (first) g_sl0[t] = idx; else g_sl1[t] = idx;
        }
        __syncthreads();
        if (tid == 0) {
            int tot = 0;
            #pragma unroll
            for (int w = 0; w < 8; w++) tot += wsum[w];
            base_s += tot;
        }
        __syncthreads();
    }
    if (tid == 0) g_cnt[e] = base_s;
}

// ---------------- launch 2: all conversions + offsets ----------------
#define NB_SPLIT 8192
#define NB_GU    36864
#define NB_DN    18432
__global__ void conv_all(const float* __restrict__ x,
                         const float* __restrict__ guw,
                         const float* __restrict__ dw,
                         const float* __restrict__ sgw,
                         const float* __restrict__ suw,
                         const float* __restrict__ sdw) {
    __shared__ float tile[32][33];
    const int b = blockIdx.x;
    const int tid = threadIdx.x;

    if (b == 0 && tid == 0) {
        int o = 0;
        #pragma unroll
        for (int e = 0; e < EE; e++) { g_off[e] = o; o += g_cnt[e]; }
    }

    if (b < NB_SPLIT) {
        size_t i = ((size_t)b * 256 + tid) * 4;
        float4 v = *(const float4*)(x + i);
        ushort4 h, l;
        splitbf(v.x, h.x, l.x); splitbf(v.y, h.y, l.y);
        splitbf(v.z, h.z, l.z); splitbf(v.w, h.w, l.w);
        *(ushort4*)(g_xhi + i) = h;
        *(ushort4*)(g_xlo + i) = l;
        return;
    }
    const int tx = tid & 31, ty = tid >> 5;
    if (b < NB_SPLIT + NB_GU) {
        int bb = b - NB_SPLIT;
        int bx = bb & 63, by = (bb >> 6) & 63, e = bb >> 12;
        int n0 = bx * 32, k0 = by * 32;
        const float* src; int ld, nsrc0;
        if (e < 8)          { src = guw + (size_t)e * 2048 * 2048; ld = 2048; nsrc0 = n0; }
        else if (n0 < 1024) { src = sgw; ld = 1024; nsrc0 = n0; }
        else                { src = suw; ld = 1024; nsrc0 = n0 - 1024; }
        #pragma unroll
        for (int j = 0; j < 4; j++) {
            int k = k0 + ty + j * 8;
            tile[ty + j * 8][tx] = src[(size_t)k * ld + nsrc0 + tx];
        }
        __syncthreads();
        #pragma unroll
        for (int j = 0; j < 4; j++) {
            int n = n0 + ty + j * 8;
            float v = tile[tx][ty + j * 8];
            unsigned short h, l;
            splitbf(v, h, l);
            size_t di = ((size_t)e * 2048 + n) * 2048 + k0 + tx;
            g_bguh[di] = h; g_bgul[di] = l;
        }
        return;
    }
    {
        int bb = b - NB_SPLIT - NB_GU;
        int bx = bb & 63, by = (bb >> 6) & 31, e = bb >> 11;
        int n0 = bx * 32, k0 = by * 32;
        const float* src = (e < 8) ? (dw + (size_t)e * 1024 * 2048) : sdw;
        #pragma unroll
        for (int j = 0; j < 4; j++) {
            int k = k0 + ty + j * 8;
            tile[ty + j * 8][tx] = src[(size_t)k * 2048 + n0 + tx];
        }
        __syncthreads();
        #pragma unroll
        for (int j = 0; j < 4; j++) {
            int n = n0 + ty + j * 8;
            float v = tile[tx][ty + j * 8];
            unsigned short h, l;
            splitbf(v, h, l);
            size_t di = ((size_t)e * 2048 + n) * 1024 + k0 + tx;
            g_bdnh[di] = h; g_bdnl[di] = l;
        }
    }
}

// ---------------- mainloop: warp tile 64x64, 192 MMA/k-tile/warp ----------------
#define MAINLOOP_KTILE(base)                                                     \
    {                                                                            \
        const uint32_t Ah = (base) + aoff;                                       \
        const uint32_t Al = Ah + ARR_B;                                          \
        const uint32_t Bh = (base) + 2 * ARR_B + boff;                           \
        const uint32_t Bl = Bh + ARR_B;                                          \
        _Pragma("unroll")                                                        \
        for (int s = 0; s < 2; s++) {                                            \
            uint32_t bhf[8][2], blf[8][2];                                       \
            _Pragma("unroll")                                                    \
            for (int ni = 0; ni < 8; ni++) {                                     \
                ldsm2(bhf[ni], Bh + ni * (8 * ROW_B) + s * 32);                  \
                ldsm2(blf[ni], Bl + ni * (8 * ROW_B) + s * 32);                  \
            }                                                                    \
            _Pragma("unroll")                                                    \
            for (int mi = 0; mi < 4; mi++) {                                     \
                uint32_t ah[4], al[4];                                           \
                ldsm4(ah, Ah + mi * (16 * ROW_B) + s * 32);                      \
                ldsm4(al, Al + mi * (16 * ROW_B) + s * 32);                      \
                _Pragma("unroll")                                                \
                for (int ni = 0; ni < 8; ni++) {                                 \
                    mma16(acc[mi][ni], ah, bhf[ni]);                             \
                    mma16(acc[mi][ni], ah, blf[ni]);                             \
                    mma16(acc[mi][ni], al, bhf[ni]);                             \
                }                                                                \
            }                                                                    \
        }                                                                        \
    }

// ---------------- launch 3: fused gate_up GEMM + SiLU + bf16-split h ----------------
// CTA tile 128m x 128n (64 gate + 64 up cols, interleaved per 16). grid (16, 32, 9)
__global__ void __launch_bounds__(128, 2)
gemm_gu_fused()
{
    const int KD = 2048;
    extern __shared__ char smem[];
    const uint32_t sb = smem_u32(smem);
    const int tid = threadIdx.x;
    const int e = blockIdx.z;
    const int row0 = blockIdx.y * 128;
    const int col0g = blockIdx.x * 64;   // gate col base (up = 1024 + same)

    int M, soff;
    const float* lpp = nullptr;
    const int* ltok = nullptr;
    if (e < 8) { M = g_cnt[e]; soff = g_off[e]; ltok = g_ltok + e * TT; lpp = g_lp + e * TT; }
    else       { M = TT; soff = RTOT; }
    if (row0 >= M) return;

    const char* src[NCHUNK]; uint32_t dst[NCHUNK];
    #pragma unroll
    for (int i = 0; i < NCHUNK; i++) {
        int idx = tid + i * 128;
        const unsigned short* rowp;
        if (idx < 1024) {        // A side
            int arr = idx >> 9, ci = idx & 511;
            int r = ci >> 2, ch = ci & 3;
            int gr = row0 + r;
            size_t tok = (e < 8) ? (size_t)((gr < M) ? ltok[gr] : 0) : (size_t)gr;
            rowp = ((arr == 0) ? g_xhi : g_xlo) + tok * DDIM;
            src[i] = (const char*)rowp + ch * 16;
            dst[i] = sb + (uint32_t)(arr * ARR_B + r * ROW_B + ch * 16);
        } else {                 // B side: 128 rows = 4 groups of (16 gate + 16 up)
            int bi = idx - 1024;
            int arr = bi >> 9, ci = bi & 511;
            int r = ci >> 2, ch = ci & 3;
            int grp = r >> 5, w = r & 31;
            int ncol = (w < 16) ? (col0g + grp * 16 + w)
                                : (1024 + col0g + grp * 16 + (w - 16));
            rowp = ((arr == 0) ? g_bguh : g_bgul) + ((size_t)e * 2048 + ncol) * (size_t)KD;
            src[i] = (const char*)rowp + ch * 16;
            dst[i] = sb + (uint32_t)(2 * ARR_B + arr * ARR_B + r * ROW_B + ch * 16);
        }
    }

    const int lane = tid & 31;
    const int g = lane >> 2, t = lane & 3;
    const int wm = (tid >> 5) & 1, wn = (tid >> 5) >> 1;   // 2 x 2 warps

    const uint32_t aoff = (uint32_t)((wm * 64 + (lane & 7) + ((lane >> 3) & 1) * 8) * ROW_B
                                     + (lane >> 4) * 16);
    const uint32_t boff = (uint32_t)((wn * 64 + (lane & 7)) * ROW_B + ((lane >> 3) & 1) * 16);

    float acc[4][8][4];
    #pragma unroll
    for (int mi = 0; mi < 4; mi++)
        #pragma unroll
        for (int ni = 0; ni < 8; ni++)
            #pragma unroll
            for (int r = 0; r < 4; r++) acc[mi][ni][r] = 0.f;

    #pragma unroll
    for (int i = 0; i < NCHUNK; i++) { CP16(dst[i], src[i]); src[i] += 64; }
    CP_COMMIT();

    const int NK = KD / KT;
    for (int it = 0; it < NK; it++) {
        CP_WAIT(0);
        __syncthreads();
        if (it + 1 < NK) {
            uint32_t so = (uint32_t)(((it + 1) & 1) * STAGE_B);
            #pragma unroll
            for (int i = 0; i < NCHUNK; i++) { CP16(dst[i] + so, src[i]); src[i] += 64; }
            CP_COMMIT();
        }
        const uint32_t base = sb + (uint32_t)((it & 1) * STAGE_B);
        MAINLOOP_KTILE(base)
    }

    // fused epilogue: h = silu(p*gate) * (p*up), split bf16, store
    // gate acc at ni {0,1,4,5}; up at ni+2
    #pragma unroll
    for (int mi = 0; mi < 4; mi++) {
        int grb = row0 + wm * 64 + mi * 16 + g;
        #pragma unroll
        for (int pass = 0; pass < 2; pass++) {
            int gr = grb + pass * 8;
            if (gr < M) {
                float p = (e < 8) ? lpp[gr] : 1.f;
                size_t slot = (size_t)(soff + gr);
                #pragma unroll
                for (int pb = 0; pb < 2; pb++) {
                    #pragma unroll
                    for (int j = 0; j < 2; j++) {
                        int ni = pb * 4 + j;
                        float gv0 = p * acc[mi][ni][pass * 2 + 0];
                        float gv1 = p * acc[mi][ni][pass * 2 + 1];
                        float uv0 = p * acc[mi][ni + 2][pass * 2 + 0];
                        float uv1 = p * acc[mi][ni + 2][pass * 2 + 1];
                        float h0 = siluf(gv0) * uv0;
                        float h1 = siluf(gv1) * uv1;
                        unsigned short h0h, h0l, h1h, h1l;
                        splitbf(h0, h0h, h0l);
                        splitbf(h1, h1h, h1l);
                        int col = col0g + (2 * wn + pb) * 16 + j * 8 + 2 * t;
                        ushort2 hh; hh.x = h0h; hh.y = h1h;
                        ushort2 hl; hl.x = h0l; hl.y = h1l;
                        *(ushort2*)(g_rhh + slot * 1024 + col) = hh;
                        *(ushort2*)(g_rhl + slot * 1024 + col) = hl;
                    }
                }
            }
        }
    }
}

// ---------------- launches 4/5: down GEMM ----------------
// ROUTED=0: shared expert (e=8), plain store to out. grid (16, 32)
// ROUTED=1: routed experts, atomicAdd to out[tok]. grid (16, 32, 8)
template <int ROUTED>
__global__ void __launch_bounds__(128, 2)
gemm_down(float* __restrict__ out)
{
    const int KD = 1024;
    extern __shared__ char smem[];
    const uint32_t sb = smem_u32(smem);
    const int tid = threadIdx.x;
    const int e = ROUTED ? blockIdx.z : 8;
    const int row0 = blockIdx.y * 128;
    const int col0 = blockIdx.x * 128;

    int M, soff;
    const int* ltok = nullptr;
    if (ROUTED) { M = g_cnt[e]; soff = g_off[e]; ltok = g_ltok + e * TT; }
    else        { M = TT; soff = RTOT; }
    if (row0 >= M) return;

    const char* src[NCHUNK]; uint32_t dst[NCHUNK];
    #pragma unroll
    for (int i = 0; i < NCHUNK; i++) {
        int idx = tid + i * 128;
        const unsigned short* rowp;
        if (idx < 1024) {
            int arr = idx >> 9, ci = idx & 511;
            int r = ci >> 2, ch = ci & 3;
            int gr = row0 + r;
            size_t slot = (size_t)(soff + ((gr < M) ? gr : 0));
            rowp = ((arr == 0) ? g_rhh : g_rhl) + slot * 1024;
            src[i] = (const char*)rowp + ch * 16;
            dst[i] = sb + (uint32_t)(arr * ARR_B + r * ROW_B + ch * 16);
        } else {
            int bi = idx - 1024;
            int arr = bi >> 9, ci = bi & 511;
            int r = ci >> 2, ch = ci & 3;
            rowp = ((arr == 0) ? g_bdnh : g_bdnl) + ((size_t)e * 2048 + col0 + r) * (size_t)KD;
            src[i] = (const char*)rowp + ch * 16;
            dst[i] = sb + (uint32_t)(2 * ARR_B + arr * ARR_B + r * ROW_B + ch * 16);
        }
    }

    const int lane = tid & 31;
    const int g = lane >> 2, t = lane & 3;
    const int wm = (tid >> 5) & 1, wn = (tid >> 5) >> 1;

    const uint32_t aoff = (uint32_t)((wm * 64 + (lane & 7) + ((lane >> 3) & 1) * 8) * ROW_B
                                     + (lane >> 4) * 16);
    const uint32_t boff = (uint32_t)((wn * 64 + (lane & 7)) * ROW_B + ((lane >> 3) & 1) * 16);

    float acc[4][8][4];
    #pragma unroll
    for (int mi = 0; mi < 4; mi++)
        #pragma unroll
        for (int ni = 0; ni < 8; ni++)
            #pragma unroll
            for (int r = 0; r < 4; r++) acc[mi][ni][r] = 0.f;

    #pragma unroll
    for (int i = 0; i < NCHUNK; i++) { CP16(dst[i], src[i]); src[i] += 64; }
    CP_COMMIT();

    const int NK = KD / KT;
    for (int it = 0; it < NK; it++) {
        CP_WAIT(0);
        __syncthreads();
        if (it + 1 < NK) {
            uint32_t so = (uint32_t)(((it + 1) & 1) * STAGE_B);
            #pragma unroll
            for (int i = 0; i < NCHUNK; i++) { CP16(dst[i] + so, src[i]); src[i] += 64; }
            CP_COMMIT();
        }
        const uint32_t base = sb + (uint32_t)((it & 1) * STAGE_B);
        MAINLOOP_KTILE(base)
    }

    #pragma unroll
    for (int mi = 0; mi < 4; mi++) {
        int gr0 = row0 + wm * 64 + mi * 16 + g;
        int gr1 = gr0 + 8;
        bool v0 = gr0 < M, v1 = gr1 < M;
        if (ROUTED) {
            int tok0 = v0 ? ltok[gr0] : 0;
            int tok1 = v1 ? ltok[gr1] : 0;
            float* d0 = out + (size_t)tok0 * 2048 + col0 + wn * 64;
            float* d1 = out + (size_t)tok1 * 2048 + col0 + wn * 64;
            #pragma unroll
            for (int ni = 0; ni < 8; ni++) {
                int cc = ni * 8 + 2 * t;
                if (v0) { atomicAdd(d0 + cc, acc[mi][ni][0]); atomicAdd(d0 + cc + 1, acc[mi][ni][1]); }
                if (v1) { atomicAdd(d1 + cc, acc[mi][ni][2]); atomicAdd(d1 + cc + 1, acc[mi][ni][3]); }
            }
        } else {
            float* d0 = out + (size_t)gr0 * 2048 + col0 + wn * 64;
            float* d1 = out + (size_t)gr1 * 2048 + col0 + wn * 64;
            #pragma unroll
            for (int ni = 0; ni < 8; ni++) {
                int cc = ni * 8 + 2 * t;
                float2 v;
                v.x = acc[mi][ni][0]; v.y = acc[mi][ni][1]; *(float2*)(d0 + cc) = v;
                v.x = acc[mi][ni][2]; v.y = acc[mi][ni][3]; *(float2*)(d1 + cc) = v;
            }
        }
    }
}

// ---------------- launch ----------------
extern "C" void kernel_launch(void* const* d_in, const int* in_sizes, int n_in,
                              void* d_out, int out_size) {
    const float* x   = (const float*)d_in[0];
    const float* rw  = (const float*)d_in[1];
    const float* guw = (const float*)d_in[2];
    const float* dw  = (const float*)d_in[3];
    const float* sgw = (const float*)d_in[4];
    const float* suw = (const float*)d_in[5];
    const float* sdw = (const float*)d_in[6];
    float* out = (float*)d_out;

    cudaFuncSetAttribute(gemm_gu_fused, cudaFuncAttributeMaxDynamicSharedMemorySize, SMEM_BYTES);
    cudaFuncSetAttribute(gemm_down<0>,  cudaFuncAttributeMaxDynamicSharedMemorySize, SMEM_BYTES);
    cudaFuncSetAttribute(gemm_down<1>,  cudaFuncAttributeMaxDynamicSharedMemorySize, SMEM_BYTES);

    router_kernel<<<TT / 8, 256>>>(x, rw);                                    // #0
    build_lists_kernel<<<EE, 256>>>();                                        // #1
    conv_all<<<NB_SPLIT + NB_GU + NB_DN, 256>>>(x, guw, dw, sgw, suw, sdw);   // #2
    gemm_gu_fused<<<dim3(16, 32, 9), 128, SMEM_BYTES>>>();                    // #3 (profiled)
    gemm_down<0><<<dim3(16, 32), 128, SMEM_BYTES>>>(out);                     // #4 shared -> store
    gemm_down<1><<<dim3(16, 32, 8), 128, SMEM_BYTES>>>(out);                  // #5 routed -> atomicAdd
}